// round 1
// baseline (speedup 1.0000x reference)
#include <cuda_runtime.h>
#include <math.h>

#define NPTS 8192
#define DIM 32
#define NCHUNK 8
#define CHUNK (NPTS / NCHUNK)   // 1024
#define TILE_I 64
#define BLOCK_J 256

// Persistent scratch (no cudaMalloc allowed)
__device__ float g_norm[2][NPTS];                 // [0]=P norms, [1]=Q norms
__device__ float g_top4[2][NPTS][NCHUNK][4];      // partial 4-smallest sq-dists
__device__ float g_rho_sq[2][NPTS];               // [0]: Y=Q (div_p), [1]: Y=P (div_q)
__device__ int   g_kp[2][NPTS];                   // counts

// ---------------------------------------------------------------- norms
__global__ void norms_kernel(const float* __restrict__ P, const float* __restrict__ Q) {
    int t = blockIdx.x * blockDim.x + threadIdx.x;
    if (t >= 2 * NPTS) return;
    int which = (t >= NPTS);
    int row = which ? t - NPTS : t;
    const float4* r4 = (const float4*)((which ? Q : P) + (size_t)row * DIM);
    float s = 0.f;
#pragma unroll
    for (int i = 0; i < DIM / 4; i++) {
        float4 v = r4[i];
        s = fmaf(v.x, v.x, s);
        s = fmaf(v.y, v.y, s);
        s = fmaf(v.z, v.z, s);
        s = fmaf(v.w, v.w, s);
    }
    g_norm[which][row] = s;
}

// ---------------------------------------------------------------- knn (4 smallest incl. self)
__global__ void knn_kernel(const float* __restrict__ P, const float* __restrict__ Q) {
    const int m = blockIdx.z;                     // 0 -> Y = Q, 1 -> Y = P
    const float* __restrict__ Y  = m ? P : Q;
    const float* __restrict__ nY = m ? g_norm[0] : g_norm[1];

    const int j = blockIdx.x * BLOCK_J + threadIdx.x;

    float yj[DIM];
    {
        const float4* rj = (const float4*)(Y + (size_t)j * DIM);
#pragma unroll
        for (int r = 0; r < DIM / 4; r++) {
            float4 v = rj[r];
            yj[4 * r + 0] = v.x; yj[4 * r + 1] = v.y;
            yj[4 * r + 2] = v.z; yj[4 * r + 3] = v.w;
        }
    }
    const float nj = nY[j];

    float m0 = 3.4e38f, m1 = 3.4e38f, m2 = 3.4e38f, m3 = 3.4e38f;

    __shared__ float4 smB[TILE_I * DIM / 4];
    __shared__ float  smN[TILE_I];

    const int ibase0 = blockIdx.y * CHUNK;
    for (int it = 0; it < CHUNK; it += TILE_I) {
        const int ibase = ibase0 + it;
        __syncthreads();
        {
            const float4* src = (const float4*)(Y + (size_t)ibase * DIM);
            for (int t = threadIdx.x; t < TILE_I * DIM / 4; t += BLOCK_J)
                smB[t] = src[t];
            if (threadIdx.x < TILE_I) smN[threadIdx.x] = nY[ibase + threadIdx.x];
        }
        __syncthreads();
#pragma unroll 2
        for (int ti = 0; ti < TILE_I; ti++) {
            const float4* b = &smB[ti * (DIM / 4)];
            float d0 = 0.f, d1 = 0.f, d2 = 0.f, d3 = 0.f;
#pragma unroll
            for (int r = 0; r < DIM / 4; r++) {
                float4 v = b[r];
                d0 = fmaf(yj[4 * r + 0], v.x, d0);
                d1 = fmaf(yj[4 * r + 1], v.y, d1);
                d2 = fmaf(yj[4 * r + 2], v.z, d2);
                d3 = fmaf(yj[4 * r + 3], v.w, d3);
            }
            float dot = (d0 + d1) + (d2 + d3);
            float s = (nj + smN[ti]) - 2.0f * dot;
            if (s < m3) {
                m3 = s;
                float t2;
                if (m3 < m2) { t2 = m2; m2 = m3; m3 = t2; }
                if (m2 < m1) { t2 = m1; m1 = m2; m2 = t2; }
                if (m1 < m0) { t2 = m0; m0 = m1; m1 = t2; }
            }
        }
    }
    float* o = g_top4[m][j][blockIdx.y];
    o[0] = m0; o[1] = m1; o[2] = m2; o[3] = m3;
}

// ---------------------------------------------------------------- merge partial top-4s
__global__ void merge_kernel() {
    int t = blockIdx.x * blockDim.x + threadIdx.x;
    if (t >= 2 * NPTS) return;
    int m = t / NPTS, j = t % NPTS;
    float m0 = 3.4e38f, m1 = 3.4e38f, m2 = 3.4e38f, m3 = 3.4e38f;
    const float* src = g_top4[m][j][0];
#pragma unroll
    for (int e = 0; e < NCHUNK * 4; e++) {
        float s = src[e];
        if (s < m3) {
            m3 = s;
            float t2;
            if (m3 < m2) { t2 = m2; m2 = m3; m3 = t2; }
            if (m2 < m1) { t2 = m1; m1 = m2; m2 = t2; }
            if (m1 < m0) { t2 = m0; m0 = m1; m1 = t2; }
        }
    }
    // rho^2 = nu^2 = max(4th-smallest sq, 1e-12)  (sqrt is monotone)
    g_rho_sq[m][j] = fmaxf(m3, 1e-12f);
    g_kp[m][j] = 0;
}

// ---------------------------------------------------------------- counts
__global__ void count_kernel(const float* __restrict__ P, const float* __restrict__ Q) {
    const int dir = blockIdx.z;                   // 0: own=Q stream=P ; 1: own=P stream=Q
    const float* __restrict__ A  = dir ? P : Q;
    const float* __restrict__ nA = dir ? g_norm[0] : g_norm[1];
    const float* __restrict__ B  = dir ? Q : P;
    const float* __restrict__ nB = dir ? g_norm[1] : g_norm[0];

    const int j = blockIdx.x * BLOCK_J + threadIdx.x;

    float yj[DIM];
    {
        const float4* rj = (const float4*)(A + (size_t)j * DIM);
#pragma unroll
        for (int r = 0; r < DIM / 4; r++) {
            float4 v = rj[r];
            yj[4 * r + 0] = v.x; yj[4 * r + 1] = v.y;
            yj[4 * r + 2] = v.z; yj[4 * r + 3] = v.w;
        }
    }
    const float nj = nA[j];
    const float rho = g_rho_sq[dir][j];           // squared threshold; s<=rho iff dist<=rho_ref

    int cnt = 0;

    __shared__ float4 smB[TILE_I * DIM / 4];
    __shared__ float  smN[TILE_I];

    const int ibase0 = blockIdx.y * CHUNK;
    for (int it = 0; it < CHUNK; it += TILE_I) {
        const int ibase = ibase0 + it;
        __syncthreads();
        {
            const float4* src = (const float4*)(B + (size_t)ibase * DIM);
            for (int t = threadIdx.x; t < TILE_I * DIM / 4; t += BLOCK_J)
                smB[t] = src[t];
            if (threadIdx.x < TILE_I) smN[threadIdx.x] = nB[ibase + threadIdx.x];
        }
        __syncthreads();
#pragma unroll 2
        for (int ti = 0; ti < TILE_I; ti++) {
            const float4* b = &smB[ti * (DIM / 4)];
            float d0 = 0.f, d1 = 0.f, d2 = 0.f, d3 = 0.f;
#pragma unroll
            for (int r = 0; r < DIM / 4; r++) {
                float4 v = b[r];
                d0 = fmaf(yj[4 * r + 0], v.x, d0);
                d1 = fmaf(yj[4 * r + 1], v.y, d1);
                d2 = fmaf(yj[4 * r + 2], v.z, d2);
                d3 = fmaf(yj[4 * r + 3], v.w, d3);
            }
            float dot = (d0 + d1) + (d2 + d3);
            float s = (nj + smN[ti]) - 2.0f * dot;
            cnt += (s <= rho) ? 1 : 0;
        }
    }
    atomicAdd(&g_kp[dir][j], cnt);
}

// ---------------------------------------------------------------- scalar epilogue
__global__ void final_kernel(float* __restrict__ out) {
    __shared__ float redf[256];
    __shared__ int   redi[256];
    const int tid = threadIdx.x;
    float vals[2];

    for (int dir = 0; dir < 2; dir++) {
        int ks = 0;
        for (int j = tid; j < NPTS; j += 256) ks += g_kp[dir][j];
        redi[tid] = ks;
        __syncthreads();
        for (int s = 128; s > 0; s >>= 1) {
            if (tid < s) redi[tid] += redi[tid + s];
            __syncthreads();
        }
        float kp_sum = (float)redi[0] + 1e-20f;
        __syncthreads();

        const float cq = 3.0f / 24576.0f;         // k_q / kq_sum (exact in fp32)
        float r = 0.f;
        for (int j = tid; j < NPTS; j += 256) {
            float ms = g_rho_sq[dir][j];
            float nu = sqrtf(ms);                 // nu = rho (nu >= 1e-6 > eps)
            float p2  = nu * nu;
            float p4  = p2 * p2;
            float p8  = p4 * p4;
            float p16 = p8 * p8;
            float p32 = p16 * p16;                // nu^d, d = 32
            float inv = 1.0f / (p32 + 1e-20f);
            float kp = (float)g_kp[dir][j];
            float p_den = fminf(fmaxf(kp / kp_sum * inv, 1e-20f), 1e10f);
            float q_den = fminf(fmaxf(cq * inv,       1e-20f), 1e10f);
            r += (p_den / q_den) * cq;
        }
        redf[tid] = r;
        __syncthreads();
        for (int s = 128; s > 0; s >>= 1) {
            if (tid < s) redf[tid] += redf[tid + s];
            __syncthreads();
        }
        float value = logf(redf[0]);              // 1/(alpha-1) = 1
        vals[dir] = fmaxf(0.0f, value);
        __syncthreads();
    }

    if (tid == 0) out[0] = fmaxf(vals[0], vals[1]);
}

// ---------------------------------------------------------------- launch
extern "C" void kernel_launch(void* const* d_in, const int* in_sizes, int n_in,
                              void* d_out, int out_size) {
    const float* P = (const float*)d_in[0];
    const float* Q = (const float*)d_in[1];
    float* out = (float*)d_out;

    norms_kernel<<<(2 * NPTS + 255) / 256, 256>>>(P, Q);
    knn_kernel  <<<dim3(NPTS / BLOCK_J, NCHUNK, 2), BLOCK_J>>>(P, Q);
    merge_kernel<<<(2 * NPTS + 255) / 256, 256>>>();
    count_kernel<<<dim3(NPTS / BLOCK_J, NCHUNK, 2), BLOCK_J>>>(P, Q);
    final_kernel<<<1, 256>>>(out);
}